// round 4
// baseline (speedup 1.0000x reference)
#include <cuda_runtime.h>
#include <cuda_fp16.h>
#include <cstdint>

// Llama4 MoE: T=2048 tokens, D=2048, F=2048, E=8 (top-1) + shared expert.
// fp16 tensor-core grouped GEMM, fp32 accumulation, fp32 router/activations.
// R2: 2-stage cp.async double-buffered tiles (dynamic smem, 54.3 KB).
// R3: removed static guard around cudaFuncSetAttribute (harness rule).

#define T_TOK  2048
#define DMODEL 2048
#define FDIM   2048
#define NEXP   8

#define BM 128
#define BN 128
#define BK 32
#define ASTRIDE 40    // halves per smem A row (32 + 8 pad); 80 B row, 16B-aligned
#define BSTRIDE 132   // floats per smem B row (128 + 4 pad); 528 B row, 16B-aligned
#define ASZ (BM * ASTRIDE)      // halves per A stage
#define BSZ (BK * BSTRIDE)      // floats per B stage
#define SMEM_BYTES (2 * ASZ * 2 + 2 * BSZ * 4)   // 54272

// ---------------- scratch (device globals; no allocation allowed) ----------
__device__ __half g_xh [(size_t)T_TOK * DMODEL];   // fp16(x)        (shared-expert A)
__device__ __half g_xg [(size_t)T_TOK * DMODEL];   // fp16(x*score), grouped by expert
__device__ float  g_gbuf[(size_t)T_TOK * FDIM];    // gate GEMM out (fp32)
__device__ float  g_ubuf[(size_t)T_TOK * FDIM];    // up   GEMM out (fp32)
__device__ __half g_h  [(size_t)T_TOK * FDIM];     // fp16(silu(g)*u)
__device__ int    g_idx[T_TOK];
__device__ int    g_perm[T_TOK];
__device__ float  g_score[T_TOK];
__device__ int    g_counts[NEXP];
__device__ int    g_cursor[NEXP];
__device__ int    g_off[NEXP + 1];
__device__ int    g_off_shared[2] = {0, T_TOK};

// ---------------------------------------------------------------------------
__global__ void k_zero() {
    if (threadIdx.x < NEXP) { g_counts[threadIdx.x] = 0; g_cursor[threadIdx.x] = 0; }
}

// Router: logits = x @ router_w [D,E]; top-1 idx (first-max tie rule), sigmoid
// score, histogram. Also emits fp16(x) for the shared expert.
__global__ void k_router(const float* __restrict__ x, const float* __restrict__ rw) {
    int t = blockIdx.x;
    const float* xr = x + (size_t)t * DMODEL;
    float acc[NEXP];
#pragma unroll
    for (int e = 0; e < NEXP; e++) acc[e] = 0.f;

    for (int k = threadIdx.x; k < DMODEL; k += 128) {
        float xv = xr[k];
        g_xh[(size_t)t * DMODEL + k] = __float2half(xv);
        const float4* w = (const float4*)(rw + (size_t)k * NEXP);
        float4 w0 = w[0], w1 = w[1];
        acc[0] += xv * w0.x; acc[1] += xv * w0.y;
        acc[2] += xv * w0.z; acc[3] += xv * w0.w;
        acc[4] += xv * w1.x; acc[5] += xv * w1.y;
        acc[6] += xv * w1.z; acc[7] += xv * w1.w;
    }
#pragma unroll
    for (int off = 16; off; off >>= 1)
#pragma unroll
        for (int e = 0; e < NEXP; e++)
            acc[e] += __shfl_xor_sync(0xffffffffu, acc[e], off);

    __shared__ float sred[4][NEXP];
    int wid = threadIdx.x >> 5, lane = threadIdx.x & 31;
    if (lane == 0)
#pragma unroll
        for (int e = 0; e < NEXP; e++) sred[wid][e] = acc[e];
    __syncthreads();
    if (threadIdx.x == 0) {
        float l[NEXP];
#pragma unroll
        for (int e = 0; e < NEXP; e++)
            l[e] = sred[0][e] + sred[1][e] + sred[2][e] + sred[3][e];
        int best = 0; float bv = l[0];
#pragma unroll
        for (int e = 1; e < NEXP; e++) if (l[e] > bv) { bv = l[e]; best = e; }
        g_idx[t] = best;
        g_score[t] = 1.f / (1.f + expf(-bv));
        atomicAdd(&g_counts[best], 1);
    }
}

__global__ void k_scan() {
    if (threadIdx.x == 0) {
        int r = 0; g_off[0] = 0;
        for (int e = 0; e < NEXP; e++) { r += g_counts[e]; g_off[e + 1] = r; }
    }
}

// Gather: token -> grouped slot; Xg[slot] = fp16(x[t] * score[t]); perm[slot]=t.
__global__ void k_gather(const float* __restrict__ x) {
    int t = blockIdx.x;
    __shared__ int sp;
    if (threadIdx.x == 0) {
        int e = g_idx[t];
        sp = g_off[e] + atomicAdd(&g_cursor[e], 1);
        g_perm[sp] = t;
    }
    __syncthreads();
    int p = sp;
    float s = g_score[t];
    const float* xr = x + (size_t)t * DMODEL;
    __half* dst = g_xg + (size_t)p * DMODEL;
    for (int k = threadIdx.x; k < DMODEL; k += 128)
        dst[k] = __float2half(xr[k] * s);
}

// ---------------------------------------------------------------------------
__device__ __forceinline__ void mma16816(float* c, const uint32_t* a, const uint32_t* b) {
    asm volatile(
        "mma.sync.aligned.m16n8k16.row.col.f32.f16.f16.f32 "
        "{%0,%1,%2,%3}, {%4,%5,%6,%7}, {%8,%9}, {%0,%1,%2,%3};\n"
        : "+f"(c[0]), "+f"(c[1]), "+f"(c[2]), "+f"(c[3])
        : "r"(a[0]), "r"(a[1]), "r"(a[2]), "r"(a[3]), "r"(b[0]), "r"(b[1]));
}

// 16-byte async copy; src_sz = 0 zero-fills the 16 destination bytes.
__device__ __forceinline__ void cp16(void* smem_dst, const void* gsrc, int src_sz) {
    uint32_t s = (uint32_t)__cvta_generic_to_shared(smem_dst);
    asm volatile("cp.async.cg.shared.global [%0], [%1], 16, %2;\n"
                 :: "r"(s), "l"(gsrc), "r"(src_sz));
}
__device__ __forceinline__ void cp_commit() {
    asm volatile("cp.async.commit_group;\n");
}
template <int N>
__device__ __forceinline__ void cp_wait() {
    asm volatile("cp.async.wait_group %0;\n" :: "n"(N));
}

// Templated grouped GEMM. A fp16 [rows,2048]; B fp32 [2048,2048] per expert;
// fp32 accum; 2-stage cp.async pipeline.
// MODE 0: gate/up -> g_gbuf/g_ubuf. MODE 1: down, plain store to out.
// MODE 2: down, scatter out[perm[r]] += v (race-free; one block per (row,col)).
template <int MODE>
__global__ __launch_bounds__(256) void k_gemm(
    int asel,                     // A: 0=g_xg, 1=g_xh, 2=g_h
    const float* __restrict__ B0, const float* __restrict__ B1,
    long bexp_stride,
    int offsel,                   // offsets: 0=g_off (routed), 1=shared {0,T}
    float* __restrict__ out)
{
    extern __shared__ char smem[];
    __half* As = (__half*)smem;                      // 2 stages of BM x ASTRIDE
    float*  Bs = (float*)(smem + 2 * ASZ * 2);       // 2 stages of BK x BSTRIDE

    const int* offs = offsel ? g_off_shared : g_off;
    int e    = blockIdx.z;
    int r0   = offs[e] + blockIdx.y * BM;
    int rend = offs[e + 1];
    if (r0 >= rend) return;

    const __half* A = (asel == 0) ? g_xg : (asel == 1) ? g_xh : g_h;

    const float* B;
    float* C = nullptr;
    int nb;
    if (MODE == 0) {
        int bx = blockIdx.x;
        if (bx < (FDIM / BN)) { B = B0 + (long)e * bexp_stride; C = g_gbuf; nb = bx * BN; }
        else                  { B = B1 + (long)e * bexp_stride; C = g_ubuf; nb = (bx - FDIM / BN) * BN; }
    } else {
        B = B0 + (long)e * bexp_stride;
        nb = blockIdx.x * BN;
    }

    int tid = threadIdx.x;
    int lane = tid & 31, wid = tid >> 5;
    int wm = wid & 1, wn = wid >> 1;       // warp tile: 64x32
    int gid = lane >> 2, tig = lane & 3;

    // per-thread load coordinates (fixed across K-blocks)
    int a_row0 = (tid * 2) >> 2,     a_cc0 = (tid * 2) & 3;
    int a_row1 = (tid * 2 + 1) >> 2, a_cc1 = (tid * 2 + 1) & 3;
    int b_k = tid >> 3, b_nc = tid & 7;

    float c[4][4][4];
#pragma unroll
    for (int mi = 0; mi < 4; mi++)
#pragma unroll
        for (int ni = 0; ni < 4; ni++)
#pragma unroll
            for (int j = 0; j < 4; j++) c[mi][ni][j] = 0.f;

    auto issue_tiles = [&](int kb, int st) {
        // A tile: 128x32 fp16; zero-fill rows beyond segment (src_sz=0)
        {
            int gr = r0 + a_row0;
            int ok = gr < rend;
            cp16(As + st * ASZ + a_row0 * ASTRIDE + a_cc0 * 8,
                 A + (size_t)(ok ? gr : r0) * DMODEL + kb * BK + a_cc0 * 8,
                 ok ? 16 : 0);
            gr = r0 + a_row1;
            ok = gr < rend;
            cp16(As + st * ASZ + a_row1 * ASTRIDE + a_cc1 * 8,
                 A + (size_t)(ok ? gr : r0) * DMODEL + kb * BK + a_cc1 * 8,
                 ok ? 16 : 0);
        }
        // B tile: 32x128 fp32 (always in range)
        {
            const float* src = B + (size_t)(kb * BK + b_k) * 2048 + nb + b_nc * 16;
            float* dst = Bs + st * BSZ + b_k * BSTRIDE + b_nc * 16;
#pragma unroll
            for (int j = 0; j < 4; j++)
                cp16(dst + j * 4, src + j * 4, 16);
        }
        cp_commit();
    };

    const int NKB = DMODEL / BK;   // 64
    issue_tiles(0, 0);

    for (int kb = 0; kb < NKB; kb++) {
        int cur = kb & 1;
        if (kb + 1 < NKB) {
            issue_tiles(kb + 1, cur ^ 1);
            cp_wait<1>();
        } else {
            cp_wait<0>();
        }
        __syncthreads();

        const __half* Ast = As + cur * ASZ;
        const float*  Bst = Bs + cur * BSZ;

#pragma unroll
        for (int ks = 0; ks < 2; ks++) {
            int k0 = ks * 16;
            uint32_t af[4][4];
#pragma unroll
            for (int mi = 0; mi < 4; mi++) {
                int r = wm * 64 + mi * 16 + gid;
                af[mi][0] = *(const uint32_t*)(Ast + r * ASTRIDE + k0 + tig * 2);
                af[mi][1] = *(const uint32_t*)(Ast + (r + 8) * ASTRIDE + k0 + tig * 2);
                af[mi][2] = *(const uint32_t*)(Ast + r * ASTRIDE + k0 + 8 + tig * 2);
                af[mi][3] = *(const uint32_t*)(Ast + (r + 8) * ASTRIDE + k0 + 8 + tig * 2);
            }
            uint32_t bf[4][2];
#pragma unroll
            for (int ni = 0; ni < 4; ni++) {
                int n = wn * 32 + ni * 8 + gid;
                __half2 p0 = __floats2half2_rn(Bst[(k0 + tig * 2)     * BSTRIDE + n],
                                               Bst[(k0 + tig * 2 + 1) * BSTRIDE + n]);
                __half2 p1 = __floats2half2_rn(Bst[(k0 + tig * 2 + 8) * BSTRIDE + n],
                                               Bst[(k0 + tig * 2 + 9) * BSTRIDE + n]);
                bf[ni][0] = *(uint32_t*)&p0;
                bf[ni][1] = *(uint32_t*)&p1;
            }
#pragma unroll
            for (int mi = 0; mi < 4; mi++)
#pragma unroll
                for (int ni = 0; ni < 4; ni++)
                    mma16816(c[mi][ni], af[mi], bf[ni]);
        }
        __syncthreads();   // stage cur may be overwritten two iterations later
    }

    // --- epilogue ---
#pragma unroll
    for (int mi = 0; mi < 4; mi++) {
#pragma unroll
        for (int ni = 0; ni < 4; ni++) {
            int rr = r0 + wm * 64 + mi * 16 + gid;
            int cc = nb + wn * 32 + ni * 8 + tig * 2;
            float* cp = c[mi][ni];
            if (MODE == 0) {
                if (rr < rend) {
                    C[(size_t)rr * FDIM + cc]     = cp[0];
                    C[(size_t)rr * FDIM + cc + 1] = cp[1];
                }
                if (rr + 8 < rend) {
                    C[(size_t)(rr + 8) * FDIM + cc]     = cp[2];
                    C[(size_t)(rr + 8) * FDIM + cc + 1] = cp[3];
                }
            } else if (MODE == 1) {
                if (rr < rend) {
                    out[(size_t)rr * DMODEL + cc]     = cp[0];
                    out[(size_t)rr * DMODEL + cc + 1] = cp[1];
                }
                if (rr + 8 < rend) {
                    out[(size_t)(rr + 8) * DMODEL + cc]     = cp[2];
                    out[(size_t)(rr + 8) * DMODEL + cc + 1] = cp[3];
                }
            } else {
                if (rr < rend) {
                    int tk = g_perm[rr];
                    float* o = out + (size_t)tk * DMODEL + cc;
                    o[0] += cp[0]; o[1] += cp[1];
                }
                if (rr + 8 < rend) {
                    int tk = g_perm[rr + 8];
                    float* o = out + (size_t)tk * DMODEL + cc;
                    o[0] += cp[2]; o[1] += cp[3];
                }
            }
        }
    }
}

// H = fp16(silu(G) * U), elementwise over T*F.
__global__ void k_swiglu() {
    size_t n = (size_t)T_TOK * FDIM;
    for (size_t i = (size_t)blockIdx.x * blockDim.x + threadIdx.x; i < n;
         i += (size_t)gridDim.x * blockDim.x) {
        float g = g_gbuf[i], u = g_ubuf[i];
        float s = g / (1.f + expf(-g));
        g_h[i] = __float2half(s * u);
    }
}

// ---------------------------------------------------------------------------
extern "C" void kernel_launch(void* const* d_in, const int* in_sizes, int n_in,
                              void* d_out, int out_size) {
    const float* x   = (const float*)d_in[0];
    const float* rw  = (const float*)d_in[1];
    const float* gw  = (const float*)d_in[2];
    const float* uw  = (const float*)d_in[3];
    const float* dw  = (const float*)d_in[4];
    const float* sgw = (const float*)d_in[5];
    const float* suw = (const float*)d_in[6];
    const float* sdw = (const float*)d_in[7];
    float* out = (float*)d_out;

    // Unconditional (no static guards per harness rules); host-side, idempotent,
    // legal during graph capture (not a stream operation).
    cudaFuncSetAttribute(k_gemm<0>, cudaFuncAttributeMaxDynamicSharedMemorySize, SMEM_BYTES);
    cudaFuncSetAttribute(k_gemm<1>, cudaFuncAttributeMaxDynamicSharedMemorySize, SMEM_BYTES);
    cudaFuncSetAttribute(k_gemm<2>, cudaFuncAttributeMaxDynamicSharedMemorySize, SMEM_BYTES);

    k_zero<<<1, 32>>>();
    k_router<<<T_TOK, 128>>>(x, rw);
    k_scan<<<1, 1>>>();
    k_gather<<<T_TOK, 128>>>(x);

    // shared expert: gate+up -> swiglu -> down (plain store initializes out)
    k_gemm<0><<<dim3(2 * FDIM / BN, T_TOK / BM, 1), 256, SMEM_BYTES>>>(1, sgw, suw, 0L, 1, nullptr);
    k_swiglu<<<2048, 256>>>();
    k_gemm<1><<<dim3(DMODEL / BN, T_TOK / BM, 1), 256, SMEM_BYTES>>>(2, sdw, nullptr, 0L, 1, out);

    // routed experts (grouped): gate+up -> swiglu -> down (scatter +=)
    k_gemm<0><<<dim3(2 * FDIM / BN, T_TOK / BM, NEXP), 256, SMEM_BYTES>>>(
        0, gw, uw, (long)DMODEL * FDIM, 0, nullptr);
    k_swiglu<<<2048, 256>>>();
    k_gemm<2><<<dim3(DMODEL / BN, T_TOK / BM, NEXP), 256, SMEM_BYTES>>>(
        2, dw, nullptr, (long)FDIM * DMODEL, 0, out);
}

// round 7
// speedup vs baseline: 1.3149x; 1.3149x over previous
#include <cuda_runtime.h>
#include <cuda_fp16.h>
#include <cstdint>

// Llama4 MoE: T=2048 tokens, D=2048, F=2048, E=8 (top-1) + shared expert.
// R4: pre-convert all weights fp32->fp16 once; all-fp16 GEMM with ldmatrix
// (A: x4, B: x4.trans), 2-stage cp.async, static smem (37.9 KB).
// R5 FIX: B tile is 8192 B -> each thread must issue TWO 16B cp.async chunks
// (R4 issued one, leaving n in [64,128) uninitialized -> NaN).
// R6: resubmit (broker timeout; fix never measured).

#define T_TOK  2048
#define DMODEL 2048
#define FDIM   2048
#define NEXP   8

#define BM 128
#define BN 128
#define BK 32
#define ASTRIDE 40     // halves per smem A row (32 + 8 pad)
#define BSTRIDE_H 136  // halves per smem B row (128 + 8 pad)
#define ASZ (BM * ASTRIDE)       // 5120 halves / stage
#define BSZ (BK * BSTRIDE_H)     // 4352 halves / stage

// ---------------- scratch (device globals; no allocation allowed) ----------
__device__ __half g_xh [(size_t)T_TOK * DMODEL];
__device__ __half g_xg [(size_t)T_TOK * DMODEL];
__device__ float  g_gbuf[(size_t)T_TOK * FDIM];
__device__ float  g_ubuf[(size_t)T_TOK * FDIM];
__device__ __half g_h  [(size_t)T_TOK * FDIM];
// fp16 weight copies (converted once per launch)
__device__ __half g_wg16[(size_t)NEXP * DMODEL * FDIM];
__device__ __half g_wu16[(size_t)NEXP * DMODEL * FDIM];
__device__ __half g_wd16[(size_t)NEXP * FDIM * DMODEL];
__device__ __half g_sg16[(size_t)DMODEL * FDIM];
__device__ __half g_su16[(size_t)DMODEL * FDIM];
__device__ __half g_sd16[(size_t)FDIM * DMODEL];
__device__ int    g_idx[T_TOK];
__device__ int    g_perm[T_TOK];
__device__ float  g_score[T_TOK];
__device__ int    g_counts[NEXP];
__device__ int    g_cursor[NEXP];
__device__ int    g_off[NEXP + 1];
__device__ int    g_off_shared[2] = {0, T_TOK};

// ---------------------------------------------------------------------------
__global__ void k_zero() {
    if (threadIdx.x < NEXP) { g_counts[threadIdx.x] = 0; g_cursor[threadIdx.x] = 0; }
}

// fp32 -> fp16 elementwise (vectorized), grid-stride.
__global__ void k_conv(const float* __restrict__ src, __half* __restrict__ dst, size_t n4) {
    for (size_t i = (size_t)blockIdx.x * blockDim.x + threadIdx.x; i < n4;
         i += (size_t)gridDim.x * blockDim.x) {
        float4 v = ((const float4*)src)[i];
        __half2 h0 = __floats2half2_rn(v.x, v.y);
        __half2 h1 = __floats2half2_rn(v.z, v.w);
        uint2 o;
        o.x = *(uint32_t*)&h0;
        o.y = *(uint32_t*)&h1;
        ((uint2*)dst)[i] = o;
    }
}

__global__ void k_router(const float* __restrict__ x, const float* __restrict__ rw) {
    int t = blockIdx.x;
    const float* xr = x + (size_t)t * DMODEL;
    float acc[NEXP];
#pragma unroll
    for (int e = 0; e < NEXP; e++) acc[e] = 0.f;

    for (int k = threadIdx.x; k < DMODEL; k += 128) {
        float xv = xr[k];
        g_xh[(size_t)t * DMODEL + k] = __float2half(xv);
        const float4* w = (const float4*)(rw + (size_t)k * NEXP);
        float4 w0 = w[0], w1 = w[1];
        acc[0] += xv * w0.x; acc[1] += xv * w0.y;
        acc[2] += xv * w0.z; acc[3] += xv * w0.w;
        acc[4] += xv * w1.x; acc[5] += xv * w1.y;
        acc[6] += xv * w1.z; acc[7] += xv * w1.w;
    }
#pragma unroll
    for (int off = 16; off; off >>= 1)
#pragma unroll
        for (int e = 0; e < NEXP; e++)
            acc[e] += __shfl_xor_sync(0xffffffffu, acc[e], off);

    __shared__ float sred[4][NEXP];
    int wid = threadIdx.x >> 5, lane = threadIdx.x & 31;
    if (lane == 0)
#pragma unroll
        for (int e = 0; e < NEXP; e++) sred[wid][e] = acc[e];
    __syncthreads();
    if (threadIdx.x == 0) {
        float l[NEXP];
#pragma unroll
        for (int e = 0; e < NEXP; e++)
            l[e] = sred[0][e] + sred[1][e] + sred[2][e] + sred[3][e];
        int best = 0; float bv = l[0];
#pragma unroll
        for (int e = 1; e < NEXP; e++) if (l[e] > bv) { bv = l[e]; best = e; }
        g_idx[t] = best;
        g_score[t] = 1.f / (1.f + expf(-bv));
        atomicAdd(&g_counts[best], 1);
    }
}

__global__ void k_scan() {
    if (threadIdx.x == 0) {
        int r = 0; g_off[0] = 0;
        for (int e = 0; e < NEXP; e++) { r += g_counts[e]; g_off[e + 1] = r; }
    }
}

__global__ void k_gather(const float* __restrict__ x) {
    int t = blockIdx.x;
    __shared__ int sp;
    if (threadIdx.x == 0) {
        int e = g_idx[t];
        sp = g_off[e] + atomicAdd(&g_cursor[e], 1);
        g_perm[sp] = t;
    }
    __syncthreads();
    int p = sp;
    float s = g_score[t];
    const float* xr = x + (size_t)t * DMODEL;
    __half* dst = g_xg + (size_t)p * DMODEL;
    for (int k = threadIdx.x; k < DMODEL; k += 128)
        dst[k] = __float2half(xr[k] * s);
}

// ---------------------------------------------------------------------------
__device__ __forceinline__ void mma16816(float* c, const uint32_t* a, const uint32_t* b) {
    asm volatile(
        "mma.sync.aligned.m16n8k16.row.col.f32.f16.f16.f32 "
        "{%0,%1,%2,%3}, {%4,%5,%6,%7}, {%8,%9}, {%0,%1,%2,%3};\n"
        : "+f"(c[0]), "+f"(c[1]), "+f"(c[2]), "+f"(c[3])
        : "r"(a[0]), "r"(a[1]), "r"(a[2]), "r"(a[3]), "r"(b[0]), "r"(b[1]));
}

__device__ __forceinline__ void ldsm_x4(uint32_t* r, const void* p) {
    uint32_t a = (uint32_t)__cvta_generic_to_shared(p);
    asm volatile("ldmatrix.sync.aligned.m8n8.x4.shared.b16 {%0,%1,%2,%3}, [%4];\n"
                 : "=r"(r[0]), "=r"(r[1]), "=r"(r[2]), "=r"(r[3]) : "r"(a));
}
__device__ __forceinline__ void ldsm_x4_t(uint32_t* r, const void* p) {
    uint32_t a = (uint32_t)__cvta_generic_to_shared(p);
    asm volatile("ldmatrix.sync.aligned.m8n8.x4.trans.shared.b16 {%0,%1,%2,%3}, [%4];\n"
                 : "=r"(r[0]), "=r"(r[1]), "=r"(r[2]), "=r"(r[3]) : "r"(a));
}

__device__ __forceinline__ void cp16(void* smem_dst, const void* gsrc, int src_sz) {
    uint32_t s = (uint32_t)__cvta_generic_to_shared(smem_dst);
    asm volatile("cp.async.cg.shared.global [%0], [%1], 16, %2;\n"
                 :: "r"(s), "l"(gsrc), "r"(src_sz));
}
__device__ __forceinline__ void cp_commit() { asm volatile("cp.async.commit_group;\n"); }
template <int N>
__device__ __forceinline__ void cp_wait() {
    asm volatile("cp.async.wait_group %0;\n" :: "n"(N));
}

// Grouped GEMM, all-fp16 operands, fp32 accum, 2-stage cp.async.
// MODE 0: gate/up -> g_gbuf/g_ubuf. MODE 1: down, plain store to out.
// MODE 2: down, scatter out[perm[r]] += v (race-free; one block per (row,col)).
template <int MODE>
__global__ __launch_bounds__(256) void k_gemm(
    int asel,                       // A: 0=g_xg, 1=g_xh, 2=g_h
    const __half* __restrict__ B0, const __half* __restrict__ B1,
    long bexp_stride,
    int offsel,                     // 0=g_off (routed), 1=shared {0,T}
    float* __restrict__ out)
{
    __shared__ __half As[2 * ASZ];
    __shared__ __half Bs[2 * BSZ];

    const int* offs = offsel ? g_off_shared : g_off;
    int e    = blockIdx.z;
    int r0   = offs[e] + blockIdx.y * BM;
    int rend = offs[e + 1];
    if (r0 >= rend) return;

    const __half* A = (asel == 0) ? g_xg : (asel == 1) ? g_xh : g_h;

    const __half* B;
    float* C = nullptr;
    int nb;
    if (MODE == 0) {
        int bx = blockIdx.x;
        if (bx < (FDIM / BN)) { B = B0 + (long)e * bexp_stride; C = g_gbuf; nb = bx * BN; }
        else                  { B = B1 + (long)e * bexp_stride; C = g_ubuf; nb = (bx - FDIM / BN) * BN; }
    } else {
        B = B0 + (long)e * bexp_stride;
        nb = blockIdx.x * BN;
    }

    int tid = threadIdx.x;
    int lane = tid & 31, wid = tid >> 5;
    int wm = wid & 1, wn = wid >> 1;       // warp tile: 64x32
    int gid = lane >> 2, tig = lane & 3;

    // per-thread cp.async coordinates
    int a_row0 = (tid * 2) >> 2,     a_cc0 = (tid * 2) & 3;      // A: 2 chunks
    int a_row1 = (tid * 2 + 1) >> 2, a_cc1 = (tid * 2 + 1) & 3;
    int b_row = tid >> 3, b_c = (tid & 7) * 16;                   // B: 2 chunks (16 halves)

    // ldmatrix lane decomposition
    int rr = lane & 7, s1 = (lane >> 3) & 1, s2 = lane >> 4;

    float c[4][4][4];
#pragma unroll
    for (int mi = 0; mi < 4; mi++)
#pragma unroll
        for (int ni = 0; ni < 4; ni++)
#pragma unroll
            for (int j = 0; j < 4; j++) c[mi][ni][j] = 0.f;

    auto issue_tiles = [&](int kb, int st) {
        // A tile: 128x32 halves (8192 B = 2 chunks/thread); zero-fill rows beyond segment
        {
            int gr = r0 + a_row0;
            int ok = gr < rend;
            cp16(As + st * ASZ + a_row0 * ASTRIDE + a_cc0 * 8,
                 A + (size_t)(ok ? gr : r0) * DMODEL + kb * BK + a_cc0 * 8,
                 ok ? 16 : 0);
            gr = r0 + a_row1;
            ok = gr < rend;
            cp16(As + st * ASZ + a_row1 * ASTRIDE + a_cc1 * 8,
                 A + (size_t)(ok ? gr : r0) * DMODEL + kb * BK + a_cc1 * 8,
                 ok ? 16 : 0);
        }
        // B tile: 32k x 128n halves (8192 B = 2 chunks/thread; always in range)
        {
            const __half* src = B + (size_t)(kb * BK + b_row) * 2048 + nb + b_c;
            __half* dst = Bs + st * BSZ + b_row * BSTRIDE_H + b_c;
            cp16(dst,     src,     16);
            cp16(dst + 8, src + 8, 16);
        }
        cp_commit();
    };

    const int NKB = DMODEL / BK;   // 64
    issue_tiles(0, 0);

    for (int kb = 0; kb < NKB; kb++) {
        int cur = kb & 1;
        if (kb + 1 < NKB) {
            issue_tiles(kb + 1, cur ^ 1);
            cp_wait<1>();
        } else {
            cp_wait<0>();
        }
        __syncthreads();

        const __half* Ast = As + cur * ASZ;
        const __half* Bst = Bs + cur * BSZ;

#pragma unroll
        for (int ks = 0; ks < 2; ks++) {
            int k0 = ks * 16;
            uint32_t af[4][4];
#pragma unroll
            for (int mi = 0; mi < 4; mi++) {
                // x4: regs 0..3 = (rows 0-7, k0) (rows 8-15, k0) (rows 0-7, k0+8) (rows 8-15, k0+8)
                int m = wm * 64 + mi * 16 + rr + s1 * 8;
                ldsm_x4(af[mi], Ast + m * ASTRIDE + k0 + s2 * 8);
            }
            uint32_t bf[4][2];
#pragma unroll
            for (int nj = 0; nj < 2; nj++) {
                // x4.trans on k-major rows: q0=(k0-7,n0-7) q1=(k8-15,n0-7) q2=(k0-7,n8-15) q3=(k8-15,n8-15)
                int kk = k0 + s1 * 8 + rr;
                int n0 = wn * 32 + nj * 16 + s2 * 8;
                uint32_t q[4];
                ldsm_x4_t(q, Bst + kk * BSTRIDE_H + n0);
                bf[nj * 2][0]     = q[0]; bf[nj * 2][1]     = q[1];
                bf[nj * 2 + 1][0] = q[2]; bf[nj * 2 + 1][1] = q[3];
            }
#pragma unroll
            for (int mi = 0; mi < 4; mi++)
#pragma unroll
                for (int ni = 0; ni < 4; ni++)
                    mma16816(c[mi][ni], af[mi], bf[ni]);
        }
        __syncthreads();
    }

    // --- epilogue ---
#pragma unroll
    for (int mi = 0; mi < 4; mi++) {
#pragma unroll
        for (int ni = 0; ni < 4; ni++) {
            int rrow = r0 + wm * 64 + mi * 16 + gid;
            int cc = nb + wn * 32 + ni * 8 + tig * 2;
            float* cp = c[mi][ni];
            if (MODE == 0) {
                if (rrow < rend) {
                    C[(size_t)rrow * FDIM + cc]     = cp[0];
                    C[(size_t)rrow * FDIM + cc + 1] = cp[1];
                }
                if (rrow + 8 < rend) {
                    C[(size_t)(rrow + 8) * FDIM + cc]     = cp[2];
                    C[(size_t)(rrow + 8) * FDIM + cc + 1] = cp[3];
                }
            } else if (MODE == 1) {
                if (rrow < rend) {
                    out[(size_t)rrow * DMODEL + cc]     = cp[0];
                    out[(size_t)rrow * DMODEL + cc + 1] = cp[1];
                }
                if (rrow + 8 < rend) {
                    out[(size_t)(rrow + 8) * DMODEL + cc]     = cp[2];
                    out[(size_t)(rrow + 8) * DMODEL + cc + 1] = cp[3];
                }
            } else {
                if (rrow < rend) {
                    int tk = g_perm[rrow];
                    float* o = out + (size_t)tk * DMODEL + cc;
                    o[0] += cp[0]; o[1] += cp[1];
                }
                if (rrow + 8 < rend) {
                    int tk = g_perm[rrow + 8];
                    float* o = out + (size_t)tk * DMODEL + cc;
                    o[0] += cp[2]; o[1] += cp[3];
                }
            }
        }
    }
}

// H = fp16(silu(G) * U)
__global__ void k_swiglu() {
    size_t n = (size_t)T_TOK * FDIM;
    for (size_t i = (size_t)blockIdx.x * blockDim.x + threadIdx.x; i < n;
         i += (size_t)gridDim.x * blockDim.x) {
        float g = g_gbuf[i], u = g_ubuf[i];
        float s = g / (1.f + expf(-g));
        g_h[i] = __float2half(s * u);
    }
}

// ---------------------------------------------------------------------------
extern "C" void kernel_launch(void* const* d_in, const int* in_sizes, int n_in,
                              void* d_out, int out_size) {
    const float* x   = (const float*)d_in[0];
    const float* rw  = (const float*)d_in[1];
    const float* gw  = (const float*)d_in[2];
    const float* uw  = (const float*)d_in[3];
    const float* dw  = (const float*)d_in[4];
    const float* sgw = (const float*)d_in[5];
    const float* suw = (const float*)d_in[6];
    const float* sdw = (const float*)d_in[7];
    float* out = (float*)d_out;

    __half *wg16, *wu16, *wd16, *sg16, *su16, *sd16;
    cudaGetSymbolAddress((void**)&wg16, g_wg16);
    cudaGetSymbolAddress((void**)&wu16, g_wu16);
    cudaGetSymbolAddress((void**)&wd16, g_wd16);
    cudaGetSymbolAddress((void**)&sg16, g_sg16);
    cudaGetSymbolAddress((void**)&su16, g_su16);
    cudaGetSymbolAddress((void**)&sd16, g_sd16);

    const size_t NR4 = (size_t)NEXP * DMODEL * FDIM / 4;
    const size_t NS4 = (size_t)DMODEL * FDIM / 4;
    k_conv<<<4096, 256>>>(gw,  wg16, NR4);
    k_conv<<<4096, 256>>>(uw,  wu16, NR4);
    k_conv<<<4096, 256>>>(dw,  wd16, NR4);
    k_conv<<<1024, 256>>>(sgw, sg16, NS4);
    k_conv<<<1024, 256>>>(suw, su16, NS4);
    k_conv<<<1024, 256>>>(sdw, sd16, NS4);

    k_zero<<<1, 32>>>();
    k_router<<<T_TOK, 128>>>(x, rw);
    k_scan<<<1, 1>>>();
    k_gather<<<T_TOK, 128>>>(x);

    // shared expert: gate+up -> swiglu -> down (plain store initializes out)
    k_gemm<0><<<dim3(2 * FDIM / BN, T_TOK / BM, 1), 256>>>(1, sg16, su16, 0L, 1, nullptr);
    k_swiglu<<<2048, 256>>>();
    k_gemm<1><<<dim3(DMODEL / BN, T_TOK / BM, 1), 256>>>(2, sd16, nullptr, 0L, 1, out);

    // routed experts (grouped): gate+up -> swiglu -> down (scatter +=)
    k_gemm<0><<<dim3(2 * FDIM / BN, T_TOK / BM, NEXP), 256>>>(
        0, wg16, wu16, (long)DMODEL * FDIM, 0, nullptr);
    k_swiglu<<<2048, 256>>>();
    k_gemm<2><<<dim3(DMODEL / BN, T_TOK / BM, NEXP), 256>>>(
        2, wd16, nullptr, (long)FDIM * DMODEL, 0, out);
}